// round 6
// baseline (speedup 1.0000x reference)
#include <cuda_runtime.h>

// ============================================================================
// Triaffine: s[b,z,x,y] = sum_{i,k,j} xb[b,x,i] * z[b,z,k] * W[i,k,j] * yb[b,y,j]
//   B=8, S=128, D=512, I=J=513 (bias), K=512, W layout [i][k][j] row-major.
// 3 stages, fp32 with packed fma.rn.f32x2, software-pipelined (cp.async double
// buffering for B, register prefetch for A, A stored duplicated so each
// LDS.128 yields two packed f32x2 operands — no per-kk MOVs).
//   k1: Xw[bx, k*513+j] = xb_all[1024,513] @ W[513, 262656]
//   k2: T[bx, z, j]     = z[b][128,512]    @ Xw[bx][512,513]
//   k3: out[b,z,x,y]    = T[bx][128,513]   @ yb[b][128,513]^T
// ============================================================================

#define BM 128
#define BN 128
#define BK 16

#define NIN   512
#define IDIM  513                 // NIN + bias
#define NW    262656              // 512*513  (k,j) flattened
#define TROW  65664               // 128*513

// Scratch (device globals — allocation-free per harness rules)
__device__ float g_Xw[268959744]; // 1024 * 262656 floats (~1.08 GB)
__device__ float g_T [67239936];  // 1024 * 128 * 513 floats (~269 MB)

static __device__ __forceinline__ unsigned sptr(const void* p) {
    return (unsigned)__cvta_generic_to_shared(p);
}

#define CP_ASYNC16Z(s, g, sz) \
    asm volatile("cp.async.ca.shared.global [%0], [%1], 16, %2;\n" :: "r"(s), "l"(g), "r"(sz))
#define CP_ASYNC4Z(s, g, sz) \
    asm volatile("cp.async.ca.shared.global [%0], [%1], 4, %2;\n"  :: "r"(s), "l"(g), "r"(sz))
#define CP_COMMIT asm volatile("cp.async.commit_group;\n" ::: "memory")
#define CP_WAIT0  asm volatile("cp.async.wait_group 0;\n"  ::: "memory")

// 8x8 per-thread micro-kernel over a BK slice. A is stored duplicated:
// As2[kk][2m]=As2[kk][2m+1]=a[m], so a 16B LDS gives two packed b64 operands.
static __device__ __forceinline__ void mma_step2(
    const float (&As2)[BK][2 * BM], const float (&Bs)[BK][BN],
    unsigned long long (&acc)[8][4], int tx, int ty)
{
#pragma unroll
    for (int kk = 0; kk < BK; kk++) {
        ulonglong2 a01 = *reinterpret_cast<const ulonglong2*>(&As2[kk][ty * 16 + 0]);
        ulonglong2 a23 = *reinterpret_cast<const ulonglong2*>(&As2[kk][ty * 16 + 4]);
        ulonglong2 a45 = *reinterpret_cast<const ulonglong2*>(&As2[kk][ty * 16 + 8]);
        ulonglong2 a67 = *reinterpret_cast<const ulonglong2*>(&As2[kk][ty * 16 + 12]);
        ulonglong2 b01 = *reinterpret_cast<const ulonglong2*>(&Bs[kk][tx * 8]);
        ulonglong2 b23 = *reinterpret_cast<const ulonglong2*>(&Bs[kk][tx * 8 + 4]);
        unsigned long long ap[8] = {a01.x, a01.y, a23.x, a23.y, a45.x, a45.y, a67.x, a67.y};
        unsigned long long bp[4] = {b01.x, b01.y, b23.x, b23.y};
#pragma unroll
        for (int i = 0; i < 8; i++) {
            asm("fma.rn.f32x2 %0, %1, %2, %0;" : "+l"(acc[i][0]) : "l"(ap[i]), "l"(bp[0]));
            asm("fma.rn.f32x2 %0, %1, %2, %0;" : "+l"(acc[i][1]) : "l"(ap[i]), "l"(bp[1]));
            asm("fma.rn.f32x2 %0, %1, %2, %0;" : "+l"(acc[i][2]) : "l"(ap[i]), "l"(bp[2]));
            asm("fma.rn.f32x2 %0, %1, %2, %0;" : "+l"(acc[i][3]) : "l"(ap[i]), "l"(bp[3]));
        }
    }
}

// ----------------------------------------------------------------------------
// k1: Xw = xb_all @ W.  grid = (8 m-tiles, 2052 n-tiles), m fastest so the 8
// CTAs sharing one W column-panel are wave-adjacent (W read ~once from DRAM).
// ----------------------------------------------------------------------------
__global__ __launch_bounds__(256, 2)
void triaffine_k1(const float* __restrict__ x, const float* __restrict__ W)
{
    __shared__ float As2[2][BK][2 * BM];  // 32 KB
    __shared__ float Bs [2][BK][BN];      // 16 KB
    const int       m0 = blockIdx.x * BM;
    const long long n0 = (long long)blockIdx.y * BN;
    const int tid = threadIdx.x;
    const int tx = tid & 15, ty = tid >> 4;
    const int a_row = tid >> 1;
    const int a_k   = (tid & 1) * 8;

    unsigned long long acc[8][4];
#pragma unroll
    for (int i = 0; i < 8; i++)
#pragma unroll
        for (int j = 0; j < 4; j++) acc[i][j] = 0ull;

    const long long arow = (long long)(m0 + a_row) * NIN;

    // A tile (k0..k0+15) for this thread -> 8 regs
    auto ldA = [&](int k0, float (&v)[8]) {
        int kb = k0 + a_k;
        if (kb + 7 < NIN) {
            float4 v0 = *reinterpret_cast<const float4*>(x + arow + kb);
            float4 v1 = *reinterpret_cast<const float4*>(x + arow + kb + 4);
            v[0] = v0.x; v[1] = v0.y; v[2] = v0.z; v[3] = v0.w;
            v[4] = v1.x; v[5] = v1.y; v[6] = v1.z; v[7] = v1.w;
        } else {
#pragma unroll
            for (int u = 0; u < 8; u++) {
                int i = kb + u;
                v[u] = (i < NIN) ? x[arow + i] : (i == NIN ? 1.0f : 0.0f);
            }
        }
    };
    auto stA = [&](int buf, const float (&v)[8]) {
#pragma unroll
        for (int u = 0; u < 8; u++)
            *reinterpret_cast<float2*>(&As2[buf][a_k + u][2 * a_row]) = make_float2(v[u], v[u]);
    };
    // B tile via cp.async (zfill for rows i >= IDIM)
    auto cpB = [&](int k0, int buf) {
#pragma unroll
        for (int c = tid; c < 512; c += 256) {
            int r = c >> 5, col = (c & 31) * 4;
            int i = k0 + r;
            int ic = i < IDIM ? i : IDIM - 1;
            const float* g = W + (long long)ic * NW + n0 + col;
            int sz = (i < IDIM) ? 16 : 0;
            CP_ASYNC16Z(sptr(&Bs[buf][r][col]), g, sz);
        }
    };

    float av[8];
    ldA(0, av);
    cpB(0, 0);
    CP_COMMIT;
    stA(0, av);

    int buf = 0;
    for (int t = 0; t < 33; t++) {
        CP_WAIT0;
        __syncthreads();
        if (t < 32) {
            ldA((t + 1) * BK, av);
            cpB((t + 1) * BK, buf ^ 1);
            CP_COMMIT;
        }
        mma_step2(As2[buf], Bs[buf], acc, tx, ty);
        if (t < 32) stA(buf ^ 1, av);
        buf ^= 1;
    }

#pragma unroll
    for (int i = 0; i < 8; i++) {
        float* crow = g_Xw + (long long)(m0 + ty * 8 + i) * NW + n0 + tx * 8;
        ulonglong2 r0; r0.x = acc[i][0]; r0.y = acc[i][1];
        ulonglong2 r1; r1.x = acc[i][2]; r1.y = acc[i][3];
        *reinterpret_cast<ulonglong2*>(crow)     = r0;
        *reinterpret_cast<ulonglong2*>(crow + 4) = r1;
    }
}

// ----------------------------------------------------------------------------
// k2: T[bx] = z[b] @ Xw[bx].  grid = (5 n-tiles, 1024 bx). N=513 -> guarded.
// Xw rows are only 4B-aligned (pitch 513 floats) -> cp.async 4B with zfill.
// ----------------------------------------------------------------------------
__global__ __launch_bounds__(256, 2)
void triaffine_k2(const float* __restrict__ zin)
{
    __shared__ float As2[2][BK][2 * BM];
    __shared__ float Bs [2][BK][BN];
    const int bx = blockIdx.y;
    const int b  = bx >> 7;
    const int n0 = blockIdx.x * BN;
    const int tid = threadIdx.x;
    const int tx = tid & 15, ty = tid >> 4;
    const int a_row = tid >> 1;
    const int a_k   = (tid & 1) * 8;

    unsigned long long acc[8][4];
#pragma unroll
    for (int i = 0; i < 8; i++)
#pragma unroll
        for (int j = 0; j < 4; j++) acc[i][j] = 0ull;

    const long long zrow  = ((long long)b * 128 + a_row) * NIN;
    const float*    Bbase = g_Xw + (long long)bx * NW;

    auto ldA = [&](int k0, float (&v)[8]) {
        float4 v0 = *reinterpret_cast<const float4*>(zin + zrow + k0 + a_k);
        float4 v1 = *reinterpret_cast<const float4*>(zin + zrow + k0 + a_k + 4);
        v[0] = v0.x; v[1] = v0.y; v[2] = v0.z; v[3] = v0.w;
        v[4] = v1.x; v[5] = v1.y; v[6] = v1.z; v[7] = v1.w;
    };
    auto stA = [&](int buf, const float (&v)[8]) {
#pragma unroll
        for (int u = 0; u < 8; u++)
            *reinterpret_cast<float2*>(&As2[buf][a_k + u][2 * a_row]) = make_float2(v[u], v[u]);
    };
    auto cpB = [&](int k0, int buf) {
#pragma unroll
        for (int q = 0; q < 8; q++) {
            int c = tid + 256 * q;
            int r = c >> 7, col = c & 127;
            int n = n0 + col;
            int nc = n < IDIM ? n : IDIM - 1;
            const float* g = Bbase + (long long)(k0 + r) * IDIM + nc;
            int sz = (n < IDIM) ? 4 : 0;
            CP_ASYNC4Z(sptr(&Bs[buf][r][col]), g, sz);
        }
    };

    float av[8];
    ldA(0, av);
    cpB(0, 0);
    CP_COMMIT;
    stA(0, av);

    int buf = 0;
    for (int t = 0; t < 32; t++) {           // K = 512 exactly
        CP_WAIT0;
        __syncthreads();
        if (t < 31) {
            ldA((t + 1) * BK, av);
            cpB((t + 1) * BK, buf ^ 1);
            CP_COMMIT;
        }
        mma_step2(As2[buf], Bs[buf], acc, tx, ty);
        if (t < 31) stA(buf ^ 1, av);
        buf ^= 1;
    }

    float* Tb = g_T + (long long)bx * TROW;
#pragma unroll
    for (int i = 0; i < 8; i++) {
        int zz = ty * 8 + i;
#pragma unroll
        for (int j = 0; j < 4; j++) {
            int c0 = n0 + tx * 8 + 2 * j;
            float lo = __uint_as_float((unsigned)(acc[i][j] & 0xffffffffull));
            float hi = __uint_as_float((unsigned)(acc[i][j] >> 32));
            if (c0 < IDIM)     Tb[zz * IDIM + c0]     = lo;
            if (c0 + 1 < IDIM) Tb[zz * IDIM + c0 + 1] = hi;
        }
    }
}

// ----------------------------------------------------------------------------
// k3: out[b,z,xx,y] = T[bx] @ yb[b]^T.  grid = 1024 bx, one 128x128 tile each.
// Both operands need transpose into SMEM -> register prefetch for both.
// ----------------------------------------------------------------------------
__global__ __launch_bounds__(256, 2)
void triaffine_k3(const float* __restrict__ yin, float* __restrict__ out)
{
    __shared__ float As2[2][BK][2 * BM];
    __shared__ float Bs [2][BK][BN];
    const int bx = blockIdx.x;
    const int b  = bx >> 7;
    const int xx = bx & 127;
    const int tid = threadIdx.x;
    const int tx = tid & 15, ty = tid >> 4;
    const int a_row = tid >> 1;
    const int a_k   = (tid & 1) * 8;

    unsigned long long acc[8][4];
#pragma unroll
    for (int i = 0; i < 8; i++)
#pragma unroll
        for (int j = 0; j < 4; j++) acc[i][j] = 0ull;

    const float*    Ta   = g_T + (long long)bx * TROW + (long long)a_row * IDIM;
    const long long yrow = ((long long)b * 128 + a_row) * NIN;

    auto ldAB = [&](int k0, float (&va)[8], float (&vb)[8]) {
        int jb = k0 + a_k;
        if (jb + 7 < NIN) {
#pragma unroll
            for (int u = 0; u < 8; u++) va[u] = Ta[jb + u];
            float4 v0 = *reinterpret_cast<const float4*>(yin + yrow + jb);
            float4 v1 = *reinterpret_cast<const float4*>(yin + yrow + jb + 4);
            vb[0] = v0.x; vb[1] = v0.y; vb[2] = v0.z; vb[3] = v0.w;
            vb[4] = v1.x; vb[5] = v1.y; vb[6] = v1.z; vb[7] = v1.w;
        } else {
#pragma unroll
            for (int u = 0; u < 8; u++) {
                int j = jb + u;
                va[u] = (j < IDIM) ? Ta[j] : 0.0f;
                vb[u] = (j < NIN) ? yin[yrow + j] : (j == NIN ? 1.0f : 0.0f);
            }
        }
    };
    auto stAB = [&](int buf, const float (&va)[8], const float (&vb)[8]) {
#pragma unroll
        for (int u = 0; u < 8; u++) {
            *reinterpret_cast<float2*>(&As2[buf][a_k + u][2 * a_row]) = make_float2(va[u], va[u]);
            Bs[buf][a_k + u][a_row] = vb[u];
        }
    };

    float av[8], bv[8];
    ldAB(0, av, bv);
    stAB(0, av, bv);

    int buf = 0;
    for (int t = 0; t < 33; t++) {
        __syncthreads();
        if (t < 32) ldAB((t + 1) * BK, av, bv);
        mma_step2(As2[buf], Bs[buf], acc, tx, ty);
        if (t < 32) stAB(buf ^ 1, av, bv);
        buf ^= 1;
    }

#pragma unroll
    for (int i = 0; i < 8; i++) {
        int zz = ty * 8 + i;
        float* o = out + ((((long long)b * 128 + zz) * 128) + xx) * 128 + tx * 8;
        ulonglong2 r0; r0.x = acc[i][0]; r0.y = acc[i][1];
        ulonglong2 r1; r1.x = acc[i][2]; r1.y = acc[i][3];
        *reinterpret_cast<ulonglong2*>(o)     = r0;
        *reinterpret_cast<ulonglong2*>(o + 4) = r1;
    }
}

// ----------------------------------------------------------------------------

extern "C" void kernel_launch(void* const* d_in, const int* in_sizes, int n_in,
                              void* d_out, int out_size)
{
    const float* x = (const float*)d_in[0];
    const float* y = (const float*)d_in[1];
    const float* z = (const float*)d_in[2];
    const float* w = (const float*)d_in[3];
    float* out = (float*)d_out;

    // Stage 1: Xw = xb_all @ W   (276 GFLOP)
    triaffine_k1<<<dim3(8, 2052), 256>>>(x, w);
    // Stage 2: T[bx] = z[b] @ Xw[bx]   (69 GFLOP)
    triaffine_k2<<<dim3(5, 1024), 256>>>(z);
    // Stage 3: out = T @ yb^T   (17 GFLOP)
    triaffine_k3<<<dim3(1024), 256>>>(y, out);
}